// round 8
// baseline (speedup 1.0000x reference)
#include <cuda_runtime.h>
#include <cuda_fp16.h>
#include <math.h>

#define Nn 100000
#define Ee 1600000
#define NSB 196          // ceil(Nn/512)
#define NBLOCKS 296      // 2 per SM on 148 SMs (GB300 has 152; co-residency guaranteed)

typedef unsigned long long ull;

// ---------------- scratch (device globals) -----------------------------------
__device__ int   g_rowptr[Nn + 1];
__device__ int   g_cursor[Nn];
__device__ int   g_colidx[Ee];
__device__ int   g_bsum[NSB];
__device__ int   g_is64;
__device__ float g_mean[(size_t)Nn * 64];   // reused as z (N x 16) in layer 3
__device__ float g_out [(size_t)Nn * 64];
__device__ float g_h   [(size_t)Nn * 64];
__device__ __half2 g_x16[(size_t)Nn * 32];
__device__ __half2 g_h16[(size_t)Nn * 32];
__device__ float g_bnsum[2][64];
__device__ float g_bnsq [2][64];
__device__ unsigned g_bar_count;   // zero-init; self-resetting
__device__ unsigned g_bar_gen;

// ---------------- helpers -----------------------------------------------------
__device__ __forceinline__ ull pack2(float v) {
    ull r; asm("mov.b64 %0, {%1, %1};" : "=l"(r) : "f"(v)); return r;
}
__device__ __forceinline__ ull fma2(ull a, ull b, ull c) {
    ull d; asm("fma.rn.f32x2 %0, %1, %2, %3;" : "=l"(d) : "l"(a), "l"(b), "l"(c)); return d;
}
__device__ __forceinline__ void unpack2(ull v, float& lo, float& hi) {
    asm("mov.b64 {%0, %1}, %2;" : "=f"(lo), "=f"(hi) : "l"(v));
}
__device__ __forceinline__ int edge_at(const void* ei, long long i, int is64) {
    return is64 ? (int)__ldg(&((const long long*)ei)[i]) : __ldg(&((const int*)ei)[i]);
}

// sense-reversing grid barrier (all blocks guaranteed co-resident)
__device__ __forceinline__ void gbar() {
    __syncthreads();
    if (threadIdx.x == 0) {
        unsigned gen = *((volatile unsigned*)&g_bar_gen);
        __threadfence();
        if (atomicAdd(&g_bar_count, 1u) == gridDim.x - 1u) {
            g_bar_count = 0u;
            __threadfence();
            atomicExch(&g_bar_gen, gen + 1u);
        } else {
            while (*((volatile unsigned*)&g_bar_gen) == gen) __nanosleep(64);
        }
        __threadfence();
    }
    __syncthreads();
}

// ---------------- the single persistent kernel --------------------------------
extern "C" __global__ void __launch_bounds__(256, 2)
gsage_mega(const float* __restrict__ x, const void* __restrict__ ei,
           const float* __restrict__ Wl1, const float* __restrict__ Wr1, const float* __restrict__ b1,
           const float* __restrict__ g1,  const float* __restrict__ be1,
           const float* __restrict__ Wl2, const float* __restrict__ Wr2, const float* __restrict__ b2,
           const float* __restrict__ g2,  const float* __restrict__ be2,
           const float* __restrict__ Wl3, const float* __restrict__ Wr3, const float* __restrict__ b3,
           float* __restrict__ out)
{
    __shared__ __align__(16) float s_w[8192];    // 32 KB: weights / scan buffer
    __shared__ __align__(16) float s_misc[128];  // bias / bn sc+sh

    const int T    = threadIdx.x;
    const int gt   = blockIdx.x * 256 + T;
    const int NT   = gridDim.x * 256;            // 75776 (multiple of 64)
    const int wg   = gt >> 5, lane = gt & 31;
    const int NW   = NT >> 5;

    // ---- P0: cursor zero + BN zero + dtype detect + x->fp16 ----
    for (int i = gt; i < Nn; i += NT) g_cursor[i] = 0;
    if (blockIdx.x == 0) {
        if (T < 64) {
            g_bnsum[0][T] = 0.f; g_bnsq[0][T] = 0.f;
            g_bnsum[1][T] = 0.f; g_bnsq[1][T] = 0.f;
        }
        if (T >= 64 && T < 96) {
            int l = T - 64;
            const long long* q = (const long long*)ei;
            long long v = q[(long long)l * 33331];
            unsigned bad = __ballot_sync(0xffffffffu, v < 0 || v >= Nn);
            if (l == 0) g_is64 = (bad == 0) ? 1 : 0;
        }
    }
    {
        const float2* p = (const float2*)x;
        for (int i = gt; i < Nn * 32; i += NT)
            g_x16[i] = __float22half2_rn(__ldg(p + i));
    }
    gbar();
    const int is64 = g_is64;

    // ---- P1: histogram of dst ----
    for (int e = gt; e < Ee; e += NT) {
        int d = edge_at(ei, (long long)Ee + e, is64);
        atomicAdd(&g_cursor[d], 1);
    }
    gbar();

    // ---- P2: block-local scans (chunks of 512, 2 per thread) ----
    {
        int* sh = (int*)s_w;
        for (int chunk = blockIdx.x; chunk < NSB; chunk += gridDim.x) {
            int i0 = chunk * 512 + T * 2;
            int v0 = (i0 < Nn)     ? g_cursor[i0]     : 0;
            int v1 = (i0 + 1 < Nn) ? g_cursor[i0 + 1] : 0;
            int ts = v0 + v1;
            sh[T] = ts;
            __syncthreads();
            for (int off = 1; off < 256; off <<= 1) {
                int t = (T >= off) ? sh[T - off] : 0;
                __syncthreads();
                sh[T] += t;
                __syncthreads();
            }
            int excl = sh[T] - ts;
            if (i0 < Nn)     g_rowptr[i0 + 1] = excl + v0;
            if (i0 + 1 < Nn) g_rowptr[i0 + 2] = excl + v0 + v1;
            if (T == 255) g_bsum[chunk] = sh[255];
            __syncthreads();
        }
    }
    gbar();

    // ---- P3: exclusive scan of block sums (block 0) ----
    if (blockIdx.x == 0) {
        int* sh = (int*)s_w;
        int v = (T < NSB) ? g_bsum[T] : 0;
        sh[T] = v;
        __syncthreads();
        for (int off = 1; off < 256; off <<= 1) {
            int t = (T >= off) ? sh[T - off] : 0;
            __syncthreads();
            sh[T] += t;
            __syncthreads();
        }
        if (T < NSB) g_bsum[T] = sh[T] - v;
    }
    gbar();

    // ---- P4: add offsets + init scatter cursor ----
    for (int i = gt; i < Nn; i += NT) {
        int fin = g_rowptr[i + 1] + g_bsum[i >> 9];
        g_rowptr[i + 1] = fin;
        if (i + 1 < Nn) g_cursor[i + 1] = fin;
    }
    if (gt == 0) { g_rowptr[0] = 0; g_cursor[0] = 0; }
    gbar();

    // ---- P5: scatter ----
    for (int e = gt; e < Ee; e += NT) {
        int d = edge_at(ei, (long long)Ee + e, is64);
        int s = edge_at(ei, e, is64);
        int pos = atomicAdd(&g_cursor[d], 1);
        g_colidx[pos] = s;
    }
    gbar();

    const float* Wls[2] = {Wl1, Wl2};
    const float* Wrs[2] = {Wr1, Wr2};
    const float* bbs[2] = {b1, b2};
    const float* gms[2] = {g1, g2};
    const float* bts[2] = {be1, be2};

    #pragma unroll 1
    for (int layer = 0; layer < 2; layer++) {
        // ---- agg: warp per node, gather fp16 table ----
        {
            const __half2* __restrict__ p = layer ? g_h16 : g_x16;
            #pragma unroll 1
            for (int w = wg; w < Nn; w += NW) {
                int beg = g_rowptr[w], end = g_rowptr[w + 1];
                float ax = 0.f, ay = 0.f;
                for (int e = beg; e < end; e += 32) {
                    int cnt = min(32, end - e);
                    int s = (lane < cnt) ? __ldg(&g_colidx[e + lane]) : 0;
                    int j = 0;
                    for (; j + 4 <= cnt; j += 4) {
                        int s0 = __shfl_sync(0xffffffffu, s, j);
                        int s1 = __shfl_sync(0xffffffffu, s, j + 1);
                        int s2 = __shfl_sync(0xffffffffu, s, j + 2);
                        int s3 = __shfl_sync(0xffffffffu, s, j + 3);
                        float2 v0 = __half22float2(__ldg(p + (size_t)s0 * 32 + lane));
                        float2 v1 = __half22float2(__ldg(p + (size_t)s1 * 32 + lane));
                        float2 v2 = __half22float2(__ldg(p + (size_t)s2 * 32 + lane));
                        float2 v3 = __half22float2(__ldg(p + (size_t)s3 * 32 + lane));
                        ax += v0.x + v1.x + v2.x + v3.x;
                        ay += v0.y + v1.y + v2.y + v3.y;
                    }
                    for (; j < cnt; j++) {
                        int sj = __shfl_sync(0xffffffffu, s, j);
                        float2 v = __half22float2(__ldg(p + (size_t)sj * 32 + lane));
                        ax += v.x; ay += v.y;
                    }
                }
                float inv = 1.0f / (float)max(end - beg, 1);
                ((float2*)g_mean)[(size_t)w * 32 + lane] = make_float2(ax * inv, ay * inv);
            }
        }
        gbar();

        // ---- dual-GEMM + L2 normalize (2 threads per row) ----
        {
            const float* __restrict__ own = layer ? (const float*)g_h : x;
            const float* Wl = Wls[layer], *Wr = Wrs[layer], *bb = bbs[layer];
            for (int i = T; i < 4096; i += 256) {
                int j = i >> 6, k = i & 63;
                s_w[k * 64 + j]        = Wl[i];   // sWl transposed
                s_w[4096 + k * 64 + j] = Wr[i];   // sWr transposed
            }
            if (T < 64) s_misc[T] = bb[T];
            __syncthreads();

            #pragma unroll 1
            for (int rp = gt; rp < 2 * Nn; rp += NT) {
                int r = rp >> 1, half = rp & 1;
                ull acc[16];
                const ull* sb2 = (const ull*)(s_misc + half * 32);
                #pragma unroll
                for (int j2 = 0; j2 < 16; j2++) acc[j2] = sb2[j2];

                const float4* m4 = (const float4*)(g_mean + (size_t)r * 64);
                const float4* h4 = (const float4*)(own + (size_t)r * 64);
                #pragma unroll 1
                for (int k4 = 0; k4 < 16; k4++) {
                    float4 m = __ldg(m4 + k4), h = __ldg(h4 + k4);
                    #pragma unroll
                    for (int kk = 0; kk < 4; kk++) {
                        float mv = kk == 0 ? m.x : kk == 1 ? m.y : kk == 2 ? m.z : m.w;
                        float hv = kk == 0 ? h.x : kk == 1 ? h.y : kk == 2 ? h.z : h.w;
                        ull mv2 = pack2(mv), hv2 = pack2(hv);
                        int k = k4 * 4 + kk;
                        const ulonglong2* wl2 = (const ulonglong2*)(s_w + k * 64) + half * 8;
                        const ulonglong2* wr2 = (const ulonglong2*)(s_w + 4096 + k * 64) + half * 8;
                        #pragma unroll
                        for (int q = 0; q < 8; q++) {
                            ulonglong2 a = wl2[q], c = wr2[q];
                            acc[q * 2 + 0] = fma2(mv2, a.x, acc[q * 2 + 0]);
                            acc[q * 2 + 1] = fma2(mv2, a.y, acc[q * 2 + 1]);
                            acc[q * 2 + 0] = fma2(hv2, c.x, acc[q * 2 + 0]);
                            acc[q * 2 + 1] = fma2(hv2, c.y, acc[q * 2 + 1]);
                        }
                    }
                }
                float v[32];
                float s = 0.f;
                #pragma unroll
                for (int j2 = 0; j2 < 16; j2++) {
                    float lo, hi;
                    unpack2(acc[j2], lo, hi);
                    v[j2 * 2] = lo; v[j2 * 2 + 1] = hi;
                    s += lo * lo + hi * hi;
                }
                s += __shfl_xor_sync(0xffffffffu, s, 1);   // partner lane has other half
                float sc = 1.0f / fmaxf(sqrtf(s), 1e-12f);
                float4* o4 = (float4*)(g_out + (size_t)r * 64 + half * 32);
                #pragma unroll
                for (int j4 = 0; j4 < 8; j4++)
                    o4[j4] = make_float4(v[j4 * 4] * sc, v[j4 * 4 + 1] * sc,
                                         v[j4 * 4 + 2] * sc, v[j4 * 4 + 3] * sc);
            }
        }
        gbar();

        // ---- bn stats ----
        {
            int col = gt & 63;       // NT multiple of 64 -> fixed column
            float s = 0.f, q = 0.f;
            for (int i = gt; i < Nn * 64; i += NT) {
                float xv = g_out[i];
                s += xv; q += xv * xv;
            }
            atomicAdd(&g_bnsum[layer][col], s);
            atomicAdd(&g_bnsq[layer][col], q);
        }
        gbar();

        // ---- bn apply + ReLU -> g_h (fp32) and g_h16 ----
        {
            if (T < 64) {
                float mu  = g_bnsum[layer][T] * (1.0f / Nn);
                float var = g_bnsq[layer][T] * (1.0f / Nn) - mu * mu;
                float sc  = rsqrtf(var + 1e-5f) * gms[layer][T];
                s_misc[T]      = sc;
                s_misc[64 + T] = bts[layer][T] - mu * sc;
            }
            __syncthreads();
            const float2* p = (const float2*)g_out;
            float2* ph = (float2*)g_h;
            for (int i = gt; i < Nn * 32; i += NT) {
                int c2 = i & 31;
                float2 v = p[i];
                float y0 = fmaxf(v.x * s_misc[c2 * 2]     + s_misc[64 + c2 * 2],     0.f);
                float y1 = fmaxf(v.y * s_misc[c2 * 2 + 1] + s_misc[64 + c2 * 2 + 1], 0.f);
                ph[i] = make_float2(y0, y1);
                g_h16[i] = __floats2half2_rn(y0, y1);
            }
        }
        gbar();
    }

    // ---- P14: layer-3 projection (fp32 h) ----
    {
        for (int i = T; i < 640; i += 256) {
            int j = i / 64, k = i % 64;
            s_w[k * 10 + j]       = Wl3[i];
            s_w[640 + k * 10 + j] = Wr3[i];
        }
        if (T < 10) s_misc[T] = b3[T];
        __syncthreads();

        #pragma unroll 1
        for (int r = gt; r < Nn; r += NT) {
            float al[10], ar[10];
            #pragma unroll
            for (int j = 0; j < 10; j++) { al[j] = 0.f; ar[j] = s_misc[j]; }
            const float4* h4 = (const float4*)(g_h + (size_t)r * 64);
            #pragma unroll 1
            for (int k4 = 0; k4 < 16; k4++) {
                float4 h = __ldg(h4 + k4);
                #pragma unroll
                for (int kk = 0; kk < 4; kk++) {
                    float hv = kk == 0 ? h.x : kk == 1 ? h.y : kk == 2 ? h.z : h.w;
                    int k = k4 * 4 + kk;
                    #pragma unroll
                    for (int j = 0; j < 10; j++) {
                        al[j] += hv * s_w[k * 10 + j];
                        ar[j] += hv * s_w[640 + k * 10 + j];
                    }
                }
            }
            float* z = g_mean + (size_t)r * 16;
            #pragma unroll
            for (int j = 0; j < 10; j++) z[j] = al[j];
            #pragma unroll
            for (int j = 10; j < 16; j++) z[j] = 0.f;
            #pragma unroll
            for (int j = 0; j < 10; j++) out[(size_t)r * 10 + j] = ar[j];
        }
    }
    gbar();

    // ---- P15: aggregate projected rows (16-wide) into out ----
    {
        int half = lane >> 4, col = lane & 15;
        #pragma unroll 1
        for (int w = wg; w < Nn; w += NW) {
            int beg = g_rowptr[w], end = g_rowptr[w + 1];
            float a = 0.f;
            for (int e = beg + half; e < end; e += 2) {
                int s = __ldg(&g_colidx[e]);
                a += __ldg(&g_mean[(size_t)s * 16 + col]);
            }
            a += __shfl_down_sync(0xffffffffu, a, 16);
            if (lane < 10) {
                float inv = 1.0f / (float)max(end - beg, 1);
                out[(size_t)w * 10 + lane] += a * inv;
            }
        }
    }
}

// ---------------- launch -----------------------------------------------------
extern "C" void kernel_launch(void* const* d_in, const int* in_sizes, int n_in,
                              void* d_out, int out_size) {
    const float* x   = (const float*)d_in[0];
    const void*  ei  = d_in[1];
    const float* Wl1 = (const float*)d_in[2];
    const float* Wr1 = (const float*)d_in[3];
    const float* b1  = (const float*)d_in[4];
    const float* g1  = (const float*)d_in[5];
    const float* be1 = (const float*)d_in[6];
    const float* Wl2 = (const float*)d_in[7];
    const float* Wr2 = (const float*)d_in[8];
    const float* b2  = (const float*)d_in[9];
    const float* g2  = (const float*)d_in[10];
    const float* be2 = (const float*)d_in[11];
    const float* Wl3 = (const float*)d_in[12];
    const float* Wr3 = (const float*)d_in[13];
    const float* b3  = (const float*)d_in[14];
    float* out = (float*)d_out;

    gsage_mega<<<NBLOCKS, 256>>>(x, ei,
                                 Wl1, Wr1, b1, g1, be1,
                                 Wl2, Wr2, b2, g2, be2,
                                 Wl3, Wr3, b3, out);
}

// round 9
// speedup vs baseline: 1.1792x; 1.1792x over previous
#include <cuda_runtime.h>
#include <cuda_fp16.h>
#include <math.h>

#define Nn 100000
#define Ee 1600000
#define NSB 196          // ceil(Nn/512)
#define NBLOCKS 296      // 2 per SM on 148 SMs
#define TPB 512

typedef unsigned long long ull;

// ---------------- scratch (device globals) -----------------------------------
__device__ int   g_rowptr[Nn + 1];
__device__ int   g_cursor[Nn];
__device__ int   g_colidx[Ee];
__device__ int   g_bsum[NSB];
__device__ int   g_is64;
__device__ float g_mean[(size_t)Nn * 64];   // reused as z (N x 16) in layer 3
__device__ float g_out [(size_t)Nn * 64];
__device__ float g_h   [(size_t)Nn * 64];
__device__ __half2 g_x16[(size_t)Nn * 32];
__device__ __half2 g_h16[(size_t)Nn * 32];
__device__ float g_bnsum[2][64];
__device__ float g_bnsq [2][64];
__device__ unsigned g_bar_count;   // zero-init; self-resetting
__device__ unsigned g_bar_gen;

// ---------------- helpers -----------------------------------------------------
__device__ __forceinline__ ull pack2(float v) {
    ull r; asm("mov.b64 %0, {%1, %1};" : "=l"(r) : "f"(v)); return r;
}
__device__ __forceinline__ ull fma2(ull a, ull b, ull c) {
    ull d; asm("fma.rn.f32x2 %0, %1, %2, %3;" : "=l"(d) : "l"(a), "l"(b), "l"(c)); return d;
}
__device__ __forceinline__ void unpack2(ull v, float& lo, float& hi) {
    asm("mov.b64 {%0, %1}, %2;" : "=f"(lo), "=f"(hi) : "l"(v));
}
__device__ __forceinline__ int edge_at(const void* ei, long long i, int is64) {
    return is64 ? (int)__ldg(&((const long long*)ei)[i]) : __ldg(&((const int*)ei)[i]);
}

// sense-reversing grid barrier (all blocks co-resident by construction)
__device__ __forceinline__ void gbar() {
    __syncthreads();
    if (threadIdx.x == 0) {
        unsigned gen = *((volatile unsigned*)&g_bar_gen);
        __threadfence();
        if (atomicAdd(&g_bar_count, 1u) == gridDim.x - 1u) {
            g_bar_count = 0u;
            __threadfence();
            atomicExch(&g_bar_gen, gen + 1u);
        } else {
            while (*((volatile unsigned*)&g_bar_gen) == gen) __nanosleep(64);
        }
        __threadfence();
    }
    __syncthreads();
}

// ---------------- the single persistent kernel --------------------------------
extern "C" __global__ void __launch_bounds__(TPB, 2)
gsage_mega(const float* __restrict__ x, const void* __restrict__ ei,
           const float* __restrict__ Wl1, const float* __restrict__ Wr1, const float* __restrict__ b1,
           const float* __restrict__ g1,  const float* __restrict__ be1,
           const float* __restrict__ Wl2, const float* __restrict__ Wr2, const float* __restrict__ b2,
           const float* __restrict__ g2,  const float* __restrict__ be2,
           const float* __restrict__ Wl3, const float* __restrict__ Wr3, const float* __restrict__ b3,
           float* __restrict__ out)
{
    __shared__ __align__(16) float s_w[8192];    // 32 KB: weights / scan buffer
    __shared__ __align__(16) float s_misc[128];  // bias / bn sc+sh

    const int T    = threadIdx.x;
    const int gt   = blockIdx.x * TPB + T;
    const int NT   = gridDim.x * TPB;            // 151552 (multiple of 64)
    const int wg   = gt >> 5, lane = gt & 31;
    const int NW   = NT >> 5;

    // ---- P0: cursor zero + BN zero + dtype detect + x->fp16 ----
    for (int i = gt; i < Nn; i += NT) g_cursor[i] = 0;
    if (blockIdx.x == 0) {
        if (T < 64) {
            g_bnsum[0][T] = 0.f; g_bnsq[0][T] = 0.f;
            g_bnsum[1][T] = 0.f; g_bnsq[1][T] = 0.f;
        }
        if (T >= 64 && T < 96) {
            int l = T - 64;
            const long long* q = (const long long*)ei;
            long long v = q[(long long)l * 33331];
            unsigned bad = __ballot_sync(0xffffffffu, v < 0 || v >= Nn);
            if (l == 0) g_is64 = (bad == 0) ? 1 : 0;
        }
    }
    {
        const float2* p = (const float2*)x;
        for (int i = gt; i < Nn * 32; i += NT)
            g_x16[i] = __float22half2_rn(__ldg(p + i));
    }
    gbar();
    const int is64 = g_is64;

    // ---- P1: histogram of dst ----
    for (int e = gt; e < Ee; e += NT) {
        int d = edge_at(ei, (long long)Ee + e, is64);
        atomicAdd(&g_cursor[d], 1);
    }
    gbar();

    // ---- P2: block-local inclusive scans over 512-element chunks ----
    {
        int* sh = (int*)s_w;
        for (int chunk = blockIdx.x; chunk < NSB; chunk += gridDim.x) {
            int i = chunk * 512 + T;
            int v = (i < Nn) ? g_cursor[i] : 0;
            sh[T] = v;
            __syncthreads();
            for (int off = 1; off < 512; off <<= 1) {
                int t = (T >= off) ? sh[T - off] : 0;
                __syncthreads();
                sh[T] += t;
                __syncthreads();
            }
            if (i < Nn) g_rowptr[i + 1] = sh[T];
            if (T == 511) g_bsum[chunk] = sh[511];
            __syncthreads();
        }
    }
    gbar();

    // ---- P3: exclusive scan of block sums (block 0, 512-wide) ----
    if (blockIdx.x == 0) {
        int* sh = (int*)s_w;
        int v = (T < NSB) ? g_bsum[T] : 0;
        sh[T] = v;
        __syncthreads();
        for (int off = 1; off < 512; off <<= 1) {
            int t = (T >= off) ? sh[T - off] : 0;
            __syncthreads();
            sh[T] += t;
            __syncthreads();
        }
        if (T < NSB) g_bsum[T] = sh[T] - v;
    }
    gbar();

    // ---- P4: add offsets + init scatter cursor ----
    for (int i = gt; i < Nn; i += NT) {
        int fin = g_rowptr[i + 1] + g_bsum[i >> 9];
        g_rowptr[i + 1] = fin;
        if (i + 1 < Nn) g_cursor[i + 1] = fin;
    }
    if (gt == 0) { g_rowptr[0] = 0; g_cursor[0] = 0; }
    gbar();

    // ---- P5: scatter ----
    for (int e = gt; e < Ee; e += NT) {
        int d = edge_at(ei, (long long)Ee + e, is64);
        int s = edge_at(ei, e, is64);
        int pos = atomicAdd(&g_cursor[d], 1);
        g_colidx[pos] = s;
    }
    gbar();

    const float* Wls[2] = {Wl1, Wl2};
    const float* Wrs[2] = {Wr1, Wr2};
    const float* bbs[2] = {b1, b2};
    const float* gms[2] = {g1, g2};
    const float* bts[2] = {be1, be2};

    #pragma unroll 1
    for (int layer = 0; layer < 2; layer++) {
        // ---- agg: warp per node, gather fp16 table ----
        {
            const __half2* __restrict__ p = layer ? g_h16 : g_x16;
            #pragma unroll 1
            for (int w = wg; w < Nn; w += NW) {
                int beg = g_rowptr[w], end = g_rowptr[w + 1];
                float ax = 0.f, ay = 0.f;
                for (int e = beg; e < end; e += 32) {
                    int cnt = min(32, end - e);
                    int s = (lane < cnt) ? __ldg(&g_colidx[e + lane]) : 0;
                    int j = 0;
                    for (; j + 4 <= cnt; j += 4) {
                        int s0 = __shfl_sync(0xffffffffu, s, j);
                        int s1 = __shfl_sync(0xffffffffu, s, j + 1);
                        int s2 = __shfl_sync(0xffffffffu, s, j + 2);
                        int s3 = __shfl_sync(0xffffffffu, s, j + 3);
                        float2 v0 = __half22float2(__ldg(p + (size_t)s0 * 32 + lane));
                        float2 v1 = __half22float2(__ldg(p + (size_t)s1 * 32 + lane));
                        float2 v2 = __half22float2(__ldg(p + (size_t)s2 * 32 + lane));
                        float2 v3 = __half22float2(__ldg(p + (size_t)s3 * 32 + lane));
                        ax += v0.x + v1.x + v2.x + v3.x;
                        ay += v0.y + v1.y + v2.y + v3.y;
                    }
                    for (; j < cnt; j++) {
                        int sj = __shfl_sync(0xffffffffu, s, j);
                        float2 v = __half22float2(__ldg(p + (size_t)sj * 32 + lane));
                        ax += v.x; ay += v.y;
                    }
                }
                float inv = 1.0f / (float)max(end - beg, 1);
                ((float2*)g_mean)[(size_t)w * 32 + lane] = make_float2(ax * inv, ay * inv);
            }
        }
        gbar();

        // ---- dual-GEMM + L2 normalize (2 threads per row; <=64 regs) ----
        {
            const float* __restrict__ own = layer ? (const float*)g_h : x;
            const float* Wl = Wls[layer], *Wr = Wrs[layer], *bb = bbs[layer];
            for (int i = T; i < 4096; i += TPB) {
                int j = i >> 6, k = i & 63;
                s_w[k * 64 + j]        = Wl[i];   // transposed
                s_w[4096 + k * 64 + j] = Wr[i];
            }
            if (T < 64) s_misc[T] = bb[T];
            __syncthreads();

            #pragma unroll 1
            for (int rp = gt; rp < 2 * Nn; rp += NT) {
                int r = rp >> 1, half = rp & 1;
                ull acc[16];
                const ull* sb2 = (const ull*)s_misc + half * 16;
                #pragma unroll
                for (int j2 = 0; j2 < 16; j2++) acc[j2] = sb2[j2];

                const float4* m4 = (const float4*)(g_mean + (size_t)r * 64);
                const float4* h4 = (const float4*)(own + (size_t)r * 64);
                #pragma unroll 1
                for (int k4 = 0; k4 < 16; k4++) {
                    float4 m = __ldg(m4 + k4), h = __ldg(h4 + k4);
                    #pragma unroll
                    for (int kk = 0; kk < 4; kk++) {
                        float mv = kk == 0 ? m.x : kk == 1 ? m.y : kk == 2 ? m.z : m.w;
                        float hv = kk == 0 ? h.x : kk == 1 ? h.y : kk == 2 ? h.z : h.w;
                        ull mv2 = pack2(mv), hv2 = pack2(hv);
                        int k = k4 * 4 + kk;
                        const ulonglong2* wl2 = (const ulonglong2*)(s_w + k * 64) + half * 8;
                        const ulonglong2* wr2 = (const ulonglong2*)(s_w + 4096 + k * 64) + half * 8;
                        #pragma unroll
                        for (int q = 0; q < 8; q++) {
                            ulonglong2 a = wl2[q], c = wr2[q];
                            acc[q * 2 + 0] = fma2(mv2, a.x, acc[q * 2 + 0]);
                            acc[q * 2 + 1] = fma2(mv2, a.y, acc[q * 2 + 1]);
                            acc[q * 2 + 0] = fma2(hv2, c.x, acc[q * 2 + 0]);
                            acc[q * 2 + 1] = fma2(hv2, c.y, acc[q * 2 + 1]);
                        }
                    }
                }
                // norm: unpack on the fly (no v[] array -> low reg pressure)
                float s = 0.f;
                #pragma unroll
                for (int j2 = 0; j2 < 16; j2++) {
                    float lo, hi;
                    unpack2(acc[j2], lo, hi);
                    s += lo * lo + hi * hi;
                }
                s += __shfl_xor_sync(0xffffffffu, s, 1);   // partner lane = other half
                float sc = 1.0f / fmaxf(sqrtf(s), 1e-12f);
                float4* o4 = (float4*)(g_out + (size_t)r * 64 + half * 32);
                #pragma unroll
                for (int j4 = 0; j4 < 8; j4++) {
                    float a0, a1, a2, a3;
                    unpack2(acc[j4 * 2],     a0, a1);
                    unpack2(acc[j4 * 2 + 1], a2, a3);
                    o4[j4] = make_float4(a0 * sc, a1 * sc, a2 * sc, a3 * sc);
                }
            }
        }
        gbar();

        // ---- bn stats ----
        {
            int col = gt & 63;       // NT multiple of 64 -> fixed column
            float s = 0.f, q = 0.f;
            for (int i = gt; i < Nn * 64; i += NT) {
                float xv = g_out[i];
                s += xv; q += xv * xv;
            }
            atomicAdd(&g_bnsum[layer][col], s);
            atomicAdd(&g_bnsq[layer][col], q);
        }
        gbar();

        // ---- bn apply + ReLU -> g_h (fp32) and g_h16 ----
        {
            if (T < 64) {
                float mu  = g_bnsum[layer][T] * (1.0f / Nn);
                float var = g_bnsq[layer][T] * (1.0f / Nn) - mu * mu;
                float sc  = rsqrtf(var + 1e-5f) * gms[layer][T];
                s_misc[T]      = sc;
                s_misc[64 + T] = bts[layer][T] - mu * sc;
            }
            __syncthreads();
            const float2* p = (const float2*)g_out;
            float2* ph = (float2*)g_h;
            for (int i = gt; i < Nn * 32; i += NT) {
                int c2 = i & 31;
                float2 v = p[i];
                float y0 = fmaxf(v.x * s_misc[c2 * 2]     + s_misc[64 + c2 * 2],     0.f);
                float y1 = fmaxf(v.y * s_misc[c2 * 2 + 1] + s_misc[64 + c2 * 2 + 1], 0.f);
                ph[i] = make_float2(y0, y1);
                g_h16[i] = __floats2half2_rn(y0, y1);
            }
        }
        gbar();
    }

    // ---- P14: layer-3 projection (fp32 h) ----
    {
        for (int i = T; i < 640; i += TPB) {
            int j = i / 64, k = i % 64;
            s_w[k * 10 + j]       = Wl3[i];
            s_w[640 + k * 10 + j] = Wr3[i];
        }
        if (T < 10) s_misc[T] = b3[T];
        __syncthreads();

        #pragma unroll 1
        for (int r = gt; r < Nn; r += NT) {
            float al[10], ar[10];
            #pragma unroll
            for (int j = 0; j < 10; j++) { al[j] = 0.f; ar[j] = s_misc[j]; }
            const float4* h4 = (const float4*)(g_h + (size_t)r * 64);
            #pragma unroll 1
            for (int k4 = 0; k4 < 16; k4++) {
                float4 h = __ldg(h4 + k4);
                #pragma unroll
                for (int kk = 0; kk < 4; kk++) {
                    float hv = kk == 0 ? h.x : kk == 1 ? h.y : kk == 2 ? h.z : h.w;
                    int k = k4 * 4 + kk;
                    #pragma unroll
                    for (int j = 0; j < 10; j++) {
                        al[j] += hv * s_w[k * 10 + j];
                        ar[j] += hv * s_w[640 + k * 10 + j];
                    }
                }
            }
            float* z = g_mean + (size_t)r * 16;
            #pragma unroll
            for (int j = 0; j < 10; j++) z[j] = al[j];
            #pragma unroll
            for (int j = 10; j < 16; j++) z[j] = 0.f;
            #pragma unroll
            for (int j = 0; j < 10; j++) out[(size_t)r * 10 + j] = ar[j];
        }
    }
    gbar();

    // ---- P15: aggregate projected rows (16-wide) into out ----
    {
        int half = lane >> 4, col = lane & 15;
        #pragma unroll 1
        for (int w = wg; w < Nn; w += NW) {
            int beg = g_rowptr[w], end = g_rowptr[w + 1];
            float a = 0.f;
            for (int e = beg + half; e < end; e += 2) {
                int s = __ldg(&g_colidx[e]);
                a += __ldg(&g_mean[(size_t)s * 16 + col]);
            }
            a += __shfl_down_sync(0xffffffffu, a, 16);
            if (lane < 10) {
                float inv = 1.0f / (float)max(end - beg, 1);
                out[(size_t)w * 10 + lane] += a * inv;
            }
        }
    }
}

// ---------------- launch -----------------------------------------------------
extern "C" void kernel_launch(void* const* d_in, const int* in_sizes, int n_in,
                              void* d_out, int out_size) {
    const float* x   = (const float*)d_in[0];
    const void*  ei  = d_in[1];
    const float* Wl1 = (const float*)d_in[2];
    const float* Wr1 = (const float*)d_in[3];
    const float* b1  = (const float*)d_in[4];
    const float* g1  = (const float*)d_in[5];
    const float* be1 = (const float*)d_in[6];
    const float* Wl2 = (const float*)d_in[7];
    const float* Wr2 = (const float*)d_in[8];
    const float* b2  = (const float*)d_in[9];
    const float* g2  = (const float*)d_in[10];
    const float* be2 = (const float*)d_in[11];
    const float* Wl3 = (const float*)d_in[12];
    const float* Wr3 = (const float*)d_in[13];
    const float* b3  = (const float*)d_in[14];
    float* out = (float*)d_out;

    gsage_mega<<<NBLOCKS, TPB>>>(x, ei,
                                 Wl1, Wr1, b1, g1, be1,
                                 Wl2, Wr2, b2, g2, be2,
                                 Wl3, Wr3, b3, out);
}